// round 12
// baseline (speedup 1.0000x reference)
#include <cuda_runtime.h>
#include <cuda_bf16.h>
#include <math.h>
#include <type_traits>

#define BB 8
#define LL 12288
#define TPB 256
#define NCHUNK 48
#define CHUNK (LL / NCHUNK)   // 256
#define G 8                   // rows per batched scan group (32-bit nibble word)

// ---------------- scratch (no allocations allowed) ----------------
// Partial sums: every cell written unconditionally by accum -> no zero-init needed.
__device__ float4 g_partN[NCHUNK][BB][LL / 4];   // 18.9 MB numerator partials
__device__ float4 g_partC[NCHUNK][LL / 4];       //  2.4 MB count partials
__device__ float  g_sumsq[BB];                   // zero-init at load; reset by finalize
__device__ int    g_done;                        // zero-init at load; reset by finalize

// ---------------- dtype detection (per-CTA, L2-hot window) ----------------
__device__ __forceinline__ unsigned word_evidence(unsigned v) {
    if (v == 0u) return 0u;
    if (v == 0x3F800000u) return 2u;                       // f32 1.0
    unsigned lo = v & 0xFFFFu, hi = v >> 16;
    if ((lo == 0u || lo == 0x3F80u) && (hi == 0u || hi == 0x3F80u)) return 4u;  // bf16
    bool bytes_ok = true;
    #pragma unroll
    for (int b = 0; b < 4; b++) { if (((v >> (8 * b)) & 0xFFu) > 1u) bytes_ok = false; }
    if (bytes_ok && v > 1u) return 1u;                     // u8 one at byte pos 1..3
    return 0u;
}

__device__ __forceinline__ int resolve_es(unsigned f) {
    if (f & 4u) return 2;   // bf16
    if (f & 2u) return 4;   // f32
    if (f & 1u) return 1;   // u8
    return 4;               // i32
}

// Scan leading 64 KB of mask (16K words). Smallest candidate buffer is 151 MB.
__device__ int detect_es_block(const unsigned int* __restrict__ w) {
    __shared__ unsigned sf;
    if (threadIdx.x == 0) sf = 0u;
    __syncthreads();
    unsigned f = 0;
    for (int i = threadIdx.x; i < 16384; i += blockDim.x)
        f |= word_evidence(w[i]);
    #pragma unroll
    for (int off = 16; off > 0; off >>= 1)
        f |= __shfl_xor_sync(0xFFFFFFFFu, f, off);
    if ((threadIdx.x & 31) == 0 && f) atomicOr(&sf, f);
    __syncthreads();
    return resolve_es(sf);
}

// ---------------- K1: sparse masked accumulate ----------------
template<int ES>
__device__ __forceinline__ void accum_body(
    const float* __restrict__ predicts,
    const float* __restrict__ adj,
    const char*  __restrict__ mask)
{
    __shared__ float s_pred[BB * CHUNK];   // 8 KB
    const int li0 = blockIdx.y * CHUNK;
    for (int i = threadIdx.x; i < BB * CHUNK; i += TPB) {
        int b = i / CHUNK, li = i % CHUNK;
        s_pred[i] = predicts[b * LL + li0 + li];
    }
    __syncthreads();

    const int lj0 = blockIdx.x * (TPB * 4) + threadIdx.x * 4;

    float acc[BB][4];
    float cnt[4];
    #pragma unroll
    for (int b = 0; b < BB; b++)
        #pragma unroll
        for (int j = 0; j < 4; j++) acc[b][j] = 0.0f;
    #pragma unroll
    for (int j = 0; j < 4; j++) cnt[j] = 0.0f;

    typedef typename std::conditional<ES == 4, uint4,
            typename std::conditional<ES == 2, uint2, unsigned>::type>::type VecT;

    auto loadrow = [&](int li) -> VecT {
        return *reinterpret_cast<const VecT*>(mask + ((size_t)li * LL + lj0) * ES);
    };
    auto rowbits = [&](VecT v) -> unsigned {
        if (ES == 4) {
            const uint4& u = reinterpret_cast<const uint4&>(v);
            return (u.x ? 1u : 0u) | (u.y ? 2u : 0u) | (u.z ? 4u : 0u) | (u.w ? 8u : 0u);
        } else if (ES == 2) {
            const uint2& u = reinterpret_cast<const uint2&>(v);
            return ((u.x & 0xFFFFu) ? 1u : 0u) | ((u.x >> 16) ? 2u : 0u)
                 | ((u.y & 0xFFFFu) ? 4u : 0u) | ((u.y >> 16) ? 8u : 0u);
        } else {
            const unsigned& u = reinterpret_cast<const unsigned&>(v);
            return ((u & 0xFFu)     ? 1u : 0u) | ((u & 0xFF00u)     ? 2u : 0u)
                 | ((u & 0xFF0000u) ? 4u : 0u) | ((u & 0xFF000000u) ? 8u : 0u);
        }
    };

    for (int s = 0; s < CHUNK; s += G) {
        // ---- batched scan: G independent LDG.128 in flight ----
        VecT v[G];
        #pragma unroll
        for (int u = 0; u < G; u++)
            v[u] = loadrow(li0 + s + u);
        unsigned mjw = 0;
        #pragma unroll
        for (int u = 0; u < G; u++)
            mjw |= rowbits(v[u]) << (4 * u);
        // ---- sparse gather + accumulate ----
        if (mjw) {
            #pragma unroll
            for (int u = 0; u < G; u++) {
                unsigned mj = (mjw >> (4 * u)) & 0xFu;
                if (mj) {
                    const int r = s + u;
                    float p[BB];
                    #pragma unroll
                    for (int b = 0; b < BB; b++)
                        p[b] = s_pred[b * CHUNK + r];
                    const size_t base = (size_t)(li0 + r) * LL + lj0;
                    #pragma unroll
                    for (int j = 0; j < 4; j++) {
                        if ((mj >> j) & 1u) {
                            float a = __ldg(&adj[base + j]);
                            cnt[j] += 1.0f;
                            #pragma unroll
                            for (int b = 0; b < BB; b++)
                                acc[b][j] += a * p[b];
                        }
                    }
                }
            }
        }
    }

    // ---- partial stores (STG.128, no atomics) ----
    const int c = blockIdx.y;
    const int q = lj0 >> 2;
    #pragma unroll
    for (int b = 0; b < BB; b++)
        g_partN[c][b][q] = make_float4(acc[b][0], acc[b][1], acc[b][2], acc[b][3]);
    g_partC[c][q] = make_float4(cnt[0], cnt[1], cnt[2], cnt[3]);
}

__global__ __launch_bounds__(TPB, 3) void accum_kernel(
    const float* __restrict__ predicts,
    const float* __restrict__ adj,
    const char*  __restrict__ mask)
{
    const int es = detect_es_block((const unsigned int*)mask);   // uniform per block
    if (es == 1)      accum_body<1>(predicts, adj, mask);
    else if (es == 2) accum_body<2>(predicts, adj, mask);
    else              accum_body<4>(predicts, adj, mask);
}

// ---------------- K2: reduce partials + finalize + scalar epilogue ----------------
__device__ __forceinline__ bool mask_nonzero(const char* mask, size_t idx, int es) {
    if (es == 1) return reinterpret_cast<const unsigned char*>(mask)[idx] != 0;
    if (es == 2) return reinterpret_cast<const unsigned short*>(mask)[idx] != 0;
    return reinterpret_cast<const unsigned int*>(mask)[idx] != 0u;
}

__global__ __launch_bounds__(256) void finalize_kernel(
    const float* __restrict__ predicts,
    const float* __restrict__ similarities,
    const char*  __restrict__ mask,
    float* __restrict__ out)
{
    const int es = detect_es_block((const unsigned int*)mask);

    __shared__ float s_sim[BB * BB];
    __shared__ bool s_last;
    if (threadIdx.x < BB * BB) s_sim[threadIdx.x] = similarities[threadIdx.x];
    __syncthreads();

    const int lj = blockIdx.x * blockDim.x + threadIdx.x;

    // sum the NCHUNK partials (coalesced across lj)
    const float* pN = reinterpret_cast<const float*>(g_partN);
    const float* pC = reinterpret_cast<const float*>(g_partC);
    float num[BB];
    float cnts = 0.0f;
    #pragma unroll
    for (int b = 0; b < BB; b++) num[b] = 0.0f;
    #pragma unroll 4
    for (int c = 0; c < NCHUNK; c++) {
        cnts += pC[c * LL + lj];
        #pragma unroll
        for (int b = 0; b < BB; b++)
            num[b] += pN[((size_t)c * BB + b) * LL + lj];
    }

    float cand[BB];
    float p_here[BB];
    float dm = mask_nonzero(mask, (size_t)lj * LL + lj, es) ? 1.0f : 0.0f;
    float inv = 1.0f / (cnts + (1.0f - dm));
    #pragma unroll
    for (int b = 0; b < BB; b++) {
        p_here[b] = predicts[b * LL + lj];
        cand[b] = (num[b] + (1.0f - dm) * p_here[b]) * inv;
    }

    #pragma unroll
    for (int b = 0; b < BB; b++) {
        float d = p_here[b];
        #pragma unroll
        for (int b2 = 0; b2 < BB; b2++)
            d -= s_sim[b * BB + b2] * cand[b2];
        float v = d * d;
        #pragma unroll
        for (int off = 16; off > 0; off >>= 1)
            v += __shfl_down_sync(0xFFFFFFFFu, v, off);
        if ((threadIdx.x & 31) == 0)
            atomicAdd(&g_sumsq[b], v);
    }

    // last-block scalar epilogue (self-resetting for graph replay)
    __threadfence();
    __syncthreads();
    if (threadIdx.x == 0) {
        int t = atomicAdd(&g_done, 1);
        s_last = (t == (int)gridDim.x - 1);
    }
    __syncthreads();
    if (s_last && threadIdx.x == 0) {
        float total = 0.0f, cntv = 0.0f;
        for (int b = 0; b < BB; b++) {
            float rs = 0.0f;
            for (int j = 0; j < BB; j++) rs += s_sim[b * BB + j];
            if (rs != 0.0f) {
                cntv += 1.0f;
                total += sqrtf(*(volatile float*)&g_sumsq[b]);
            }
        }
        out[0] = (cntv == 0.0f) ? 0.0f : (total / fmaxf(cntv, 1.0f));
        #pragma unroll
        for (int b = 0; b < BB; b++) g_sumsq[b] = 0.0f;   // reset for next replay
        g_done = 0;
    }
}

// ---------------- launch ----------------
extern "C" void kernel_launch(void* const* d_in, const int* in_sizes, int n_in,
                              void* d_out, int out_size)
{
    const float* predicts = (const float*)d_in[0];
    const float* sim      = (const float*)d_in[1];
    const float* adj      = (const float*)d_in[2];
    const char*  mask     = (const char*)d_in[3];
    float* out = (float*)d_out;

    (void)in_sizes; (void)n_in; (void)out_size;

    dim3 grid1(LL / (TPB * 4), NCHUNK);   // (12, 48) = 576 CTAs
    accum_kernel<<<grid1, TPB>>>(predicts, adj, mask);

    finalize_kernel<<<LL / 256, 256>>>(predicts, sim, mask, out);
}

// round 13
// speedup vs baseline: 1.6493x; 1.6493x over previous
#include <cuda_runtime.h>
#include <cuda_bf16.h>
#include <math.h>
#include <type_traits>

#define BB 8
#define LL 12288

// ---------------- scratch (no allocations allowed) ----------------
__device__ float g_numer[BB * LL];
__device__ float g_counts[LL];
__device__ float g_sumsq[BB];
__device__ unsigned g_flags = 0u;  // bit0=u8, bit1=f32, bit2=bf16 (reset by finalize)
__device__ int g_done = 0;         // finalize completion counter (self-resetting)

__device__ __forceinline__ int resolve_es(unsigned f) {
    if (f & 4u) return 2;   // bf16
    if (f & 2u) return 4;   // f32
    if (f & 1u) return 1;   // u8
    return 4;               // i32
}

// ---------------- K_prep: zero scratch + parallel dtype scan ----------------
__global__ __launch_bounds__(256) void prep_kernel(const unsigned int* __restrict__ w) {
    const int gid = blockIdx.x * blockDim.x + threadIdx.x;
    const int gsz = gridDim.x * blockDim.x;

    const int total = BB * LL + LL + BB;
    for (int i = gid; i < total; i += gsz) {
        if (i < BB * LL)            g_numer[i] = 0.0f;
        else if (i < BB * LL + LL)  g_counts[i - BB * LL] = 0.0f;
        else                        g_sumsq[i - BB * LL - LL] = 0.0f;
    }

    const int N = 1 << 18;   // 1 MB evidence window (smallest candidate buffer 151 MB)
    unsigned f = 0;
    for (int i = gid; i < N; i += gsz) {
        unsigned v = w[i];
        if (v == 0u) continue;
        if (v == 0x3F800000u) { f |= 2u; continue; }            // f32 1.0
        unsigned lo = v & 0xFFFFu, hi = v >> 16;
        if ((lo == 0u || lo == 0x3F80u) && (hi == 0u || hi == 0x3F80u)) { f |= 4u; continue; }
        bool bytes_ok = true;
        #pragma unroll
        for (int b = 0; b < 4; b++) { if (((v >> (8 * b)) & 0xFFu) > 1u) bytes_ok = false; }
        if (bytes_ok && v > 1u) f |= 1u;                        // u8 evidence
    }
    #pragma unroll
    for (int off = 16; off > 0; off >>= 1)
        f |= __shfl_xor_sync(0xFFFFFFFFu, f, off);
    if ((threadIdx.x & 31) == 0 && f) atomicOr(&g_flags, f);
}

// ---------------- K1: sparse masked accumulate (R10 config + fast-path scan) ----------------
#define TPB 256
#define NCHUNK 48
#define CHUNK (LL / NCHUNK)   // 256
#define UROW 2                // rows per pipelined batch

template<int ES>
__device__ __forceinline__ void accum_body(
    const float* __restrict__ predicts,
    const float* __restrict__ adj,
    const char*  __restrict__ mask)
{
    __shared__ __align__(16) float s_pred[CHUNK][BB];   // 8 KB, transposed: row-major per li
    const int li0 = blockIdx.y * CHUNK;
    for (int i = threadIdx.x; i < BB * CHUNK; i += TPB) {
        int li = i >> 3, b = i & 7;
        s_pred[li][b] = predicts[b * LL + li0 + li];
    }
    __syncthreads();

    const int lj0 = blockIdx.x * (TPB * 4) + threadIdx.x * 4;

    float acc[BB][4];
    float cnt[4];
    #pragma unroll
    for (int b = 0; b < BB; b++)
        #pragma unroll
        for (int j = 0; j < 4; j++) acc[b][j] = 0.0f;
    #pragma unroll
    for (int j = 0; j < 4; j++) cnt[j] = 0.0f;

    typedef typename std::conditional<ES == 4, uint4,
            typename std::conditional<ES == 2, uint2, unsigned>::type>::type VecT;

    auto loadrow = [&](int li) -> VecT {
        return *reinterpret_cast<const VecT*>(mask + ((size_t)li * LL + lj0) * ES);
    };
    auto anyset = [&](VecT v) -> unsigned {     // cheap OR-tree: nonzero iff any lj hit
        if (ES == 4) {
            const uint4& u = reinterpret_cast<const uint4&>(v);
            return u.x | u.y | u.z | u.w;
        } else if (ES == 2) {
            const uint2& u = reinterpret_cast<const uint2&>(v);
            return u.x | u.y;
        } else {
            return reinterpret_cast<const unsigned&>(v);
        }
    };
    auto wordhit = [&](VecT v, int j) -> bool { // per-lj predicate, slow path only
        if (ES == 4) {
            const uint4& u = reinterpret_cast<const uint4&>(v);
            return (j == 0 ? u.x : j == 1 ? u.y : j == 2 ? u.z : u.w) != 0u;
        } else if (ES == 2) {
            const uint2& u = reinterpret_cast<const uint2&>(v);
            unsigned h = (j < 2) ? u.x : u.y;
            return ((j & 1) ? (h >> 16) : (h & 0xFFFFu)) != 0u;
        } else {
            unsigned u = reinterpret_cast<const unsigned&>(v);
            return ((u >> (8 * j)) & 0xFFu) != 0u;
        }
    };

    auto process = [&](VecT v, int r) {         // r = row offset in chunk (warp-uniform)
        if (anyset(v)) {
            // 8 predicts via 2 broadcast LDS.128 (r uniform across warp)
            float4 pA = *reinterpret_cast<const float4*>(&s_pred[r][0]);
            float4 pB = *reinterpret_cast<const float4*>(&s_pred[r][4]);
            float p[BB] = {pA.x, pA.y, pA.z, pA.w, pB.x, pB.y, pB.z, pB.w};
            const size_t base = (size_t)(li0 + r) * LL + lj0;
            #pragma unroll
            for (int j = 0; j < 4; j++) {
                if (wordhit(v, j)) {
                    float a = __ldg(&adj[base + j]);
                    cnt[j] += 1.0f;
                    #pragma unroll
                    for (int b = 0; b < BB; b++)
                        acc[b][j] += a * p[b];
                }
            }
        }
    };

    // software pipeline: next batch's loads in flight while current is processed
    VecT cur[UROW];
    #pragma unroll
    for (int u = 0; u < UROW; u++) cur[u] = loadrow(li0 + u);

    for (int li = li0; li < li0 + CHUNK; li += UROW) {
        VecT nxt[UROW];
        const bool has_next = (li + UROW) < (li0 + CHUNK);
        if (has_next) {
            #pragma unroll
            for (int u = 0; u < UROW; u++) nxt[u] = loadrow(li + UROW + u);
        }
        #pragma unroll
        for (int u = 0; u < UROW; u++)
            process(cur[u], li - li0 + u);
        if (has_next) {
            #pragma unroll
            for (int u = 0; u < UROW; u++) cur[u] = nxt[u];
        }
    }

    #pragma unroll
    for (int j = 0; j < 4; j++) {
        atomicAdd(&g_counts[lj0 + j], cnt[j]);
        #pragma unroll
        for (int b = 0; b < BB; b++)
            atomicAdd(&g_numer[b * LL + lj0 + j], acc[b][j]);
    }
}

__global__ __launch_bounds__(TPB, 4) void accum_kernel(
    const float* __restrict__ predicts,
    const float* __restrict__ adj,
    const char*  __restrict__ mask)
{
    const int es = resolve_es(g_flags);   // uniform
    if (es == 1)      accum_body<1>(predicts, adj, mask);
    else if (es == 2) accum_body<2>(predicts, adj, mask);
    else              accum_body<4>(predicts, adj, mask);
}

// ---------------- K2: finalize + fused scalar epilogue ----------------
__device__ __forceinline__ bool mask_nonzero(const char* mask, size_t idx, int es) {
    if (es == 1) return reinterpret_cast<const unsigned char*>(mask)[idx] != 0;
    if (es == 2) return reinterpret_cast<const unsigned short*>(mask)[idx] != 0;
    return reinterpret_cast<const unsigned int*>(mask)[idx] != 0u;
}

__global__ __launch_bounds__(256) void finalize_kernel(
    const float* __restrict__ predicts,
    const float* __restrict__ similarities,
    const char*  __restrict__ mask,
    float* __restrict__ out)
{
    __shared__ float s_sim[BB * BB];
    __shared__ bool s_last;
    if (threadIdx.x < BB * BB) s_sim[threadIdx.x] = similarities[threadIdx.x];
    __syncthreads();

    const int es = resolve_es(g_flags);
    const int lj = blockIdx.x * blockDim.x + threadIdx.x;

    float cand[BB];
    float p_here[BB];
    float dm = mask_nonzero(mask, (size_t)lj * LL + lj, es) ? 1.0f : 0.0f;
    float inv = 1.0f / (g_counts[lj] + (1.0f - dm));
    #pragma unroll
    for (int b = 0; b < BB; b++) {
        p_here[b] = predicts[b * LL + lj];
        cand[b] = (g_numer[b * LL + lj] + (1.0f - dm) * p_here[b]) * inv;
    }

    #pragma unroll
    for (int b = 0; b < BB; b++) {
        float d = p_here[b];
        #pragma unroll
        for (int b2 = 0; b2 < BB; b2++)
            d -= s_sim[b * BB + b2] * cand[b2];
        float v = d * d;
        #pragma unroll
        for (int off = 16; off > 0; off >>= 1)
            v += __shfl_down_sync(0xFFFFFFFFu, v, off);
        if ((threadIdx.x & 31) == 0)
            atomicAdd(&g_sumsq[b], v);
    }

    __threadfence();
    __syncthreads();
    if (threadIdx.x == 0) {
        int t = atomicAdd(&g_done, 1);
        s_last = (t == (int)gridDim.x - 1);
    }
    __syncthreads();
    if (s_last && threadIdx.x == 0) {
        float total = 0.0f, cntv = 0.0f;
        for (int b = 0; b < BB; b++) {
            float rs = 0.0f;
            for (int j = 0; j < BB; j++) rs += s_sim[b * BB + j];
            if (rs != 0.0f) {
                cntv += 1.0f;
                total += sqrtf(*(volatile float*)&g_sumsq[b]);
            }
        }
        out[0] = (cntv == 0.0f) ? 0.0f : (total / fmaxf(cntv, 1.0f));
        g_done = 0;      // reset for graph replay
        g_flags = 0u;
    }
}

// ---------------- launch ----------------
extern "C" void kernel_launch(void* const* d_in, const int* in_sizes, int n_in,
                              void* d_out, int out_size)
{
    const float* predicts = (const float*)d_in[0];
    const float* sim      = (const float*)d_in[1];
    const float* adj      = (const float*)d_in[2];
    const char*  mask     = (const char*)d_in[3];
    float* out = (float*)d_out;

    (void)in_sizes; (void)n_in; (void)out_size;

    prep_kernel<<<304, 256>>>((const unsigned int*)mask);

    dim3 grid1(LL / (TPB * 4), NCHUNK);   // (12, 48) = 576 CTAs
    accum_kernel<<<grid1, TPB>>>(predicts, adj, mask);

    finalize_kernel<<<LL / 256, 256>>>(predicts, sim, mask, out);
}

// round 14
// speedup vs baseline: 1.8015x; 1.0923x over previous
#include <cuda_runtime.h>
#include <cuda_bf16.h>
#include <math.h>
#include <type_traits>

#define BB 8
#define LL 12288

// ---------------- scratch (no allocations allowed) ----------------
__device__ float g_numer[BB * LL];
__device__ float g_counts[LL];
__device__ float g_sumsq[BB];
__device__ unsigned g_flags = 0u;  // bit0=u8, bit1=f32, bit2=bf16 (reset by finalize)
__device__ int g_done = 0;         // finalize completion counter (self-resetting)

__device__ __forceinline__ int resolve_es(unsigned f) {
    if (f & 4u) return 2;   // bf16
    if (f & 2u) return 4;   // f32
    if (f & 1u) return 1;   // u8
    return 4;               // i32
}

// ---------------- K_prep: zero scratch + parallel dtype scan ----------------
__global__ __launch_bounds__(256) void prep_kernel(const unsigned int* __restrict__ w) {
    const int gid = blockIdx.x * blockDim.x + threadIdx.x;
    const int gsz = gridDim.x * blockDim.x;

    const int total = BB * LL + LL + BB;
    for (int i = gid; i < total; i += gsz) {
        if (i < BB * LL)            g_numer[i] = 0.0f;
        else if (i < BB * LL + LL)  g_counts[i - BB * LL] = 0.0f;
        else                        g_sumsq[i - BB * LL - LL] = 0.0f;
    }

    const int N = 1 << 18;   // 1 MB evidence window (smallest candidate buffer 151 MB)
    unsigned f = 0;
    for (int i = gid; i < N; i += gsz) {
        unsigned v = w[i];
        if (v == 0u) continue;
        if (v == 0x3F800000u) { f |= 2u; continue; }            // f32 1.0
        unsigned lo = v & 0xFFFFu, hi = v >> 16;
        if ((lo == 0u || lo == 0x3F80u) && (hi == 0u || hi == 0x3F80u)) { f |= 4u; continue; }
        bool bytes_ok = true;
        #pragma unroll
        for (int b = 0; b < 4; b++) { if (((v >> (8 * b)) & 0xFFu) > 1u) bytes_ok = false; }
        if (bytes_ok && v > 1u) f |= 1u;                        // u8 evidence
    }
    #pragma unroll
    for (int off = 16; off > 0; off >>= 1)
        f |= __shfl_xor_sync(0xFFFFFFFFu, f, off);
    if ((threadIdx.x & 31) == 0 && f) atomicOr(&g_flags, f);
}

// ---------------- K1: sparse masked accumulate (2 lj/thread, deep pipeline) ----------------
#define TPB 256
#define NCHUNK 24
#define CHUNK (LL / NCHUNK)   // 512
#define UROW 4                // rows per pipelined batch

template<int ES>
__device__ __forceinline__ void accum_body(
    const float* __restrict__ predicts,
    const float* __restrict__ adj,
    const char*  __restrict__ mask)
{
    __shared__ __align__(16) float s_pred[CHUNK][BB];   // 16 KB, transposed
    const int li0 = blockIdx.y * CHUNK;
    for (int i = threadIdx.x; i < BB * CHUNK; i += TPB) {
        int li = i >> 3, b = i & 7;
        s_pred[li][b] = predicts[b * LL + li0 + li];
    }
    __syncthreads();

    const int lj0 = blockIdx.x * (TPB * 2) + threadIdx.x * 2;   // 2 lj per thread

    float acc[BB][2];
    float cnt[2];
    #pragma unroll
    for (int b = 0; b < BB; b++)
        #pragma unroll
        for (int j = 0; j < 2; j++) acc[b][j] = 0.0f;
    cnt[0] = cnt[1] = 0.0f;

    typedef typename std::conditional<ES == 4, uint2,
            typename std::conditional<ES == 2, unsigned, unsigned short>::type>::type VecT;

    auto loadrow = [&](int li) -> VecT {
        return *reinterpret_cast<const VecT*>(mask + ((size_t)li * LL + lj0) * ES);
    };
    auto anyset = [&](VecT v) -> unsigned {
        if (ES == 4) {
            const uint2& u = reinterpret_cast<const uint2&>(v);
            return u.x | u.y;
        } else if (ES == 2) {
            return reinterpret_cast<const unsigned&>(v);
        } else {
            return (unsigned)reinterpret_cast<const unsigned short&>(v);
        }
    };
    auto wordhit = [&](VecT v, int j) -> bool {
        if (ES == 4) {
            const uint2& u = reinterpret_cast<const uint2&>(v);
            return (j == 0 ? u.x : u.y) != 0u;
        } else if (ES == 2) {
            unsigned u = reinterpret_cast<const unsigned&>(v);
            return ((j == 0) ? (u & 0xFFFFu) : (u >> 16)) != 0u;
        } else {
            unsigned u = (unsigned)reinterpret_cast<const unsigned short&>(v);
            return ((u >> (8 * j)) & 0xFFu) != 0u;
        }
    };

    auto process = [&](VecT v, int r) {          // r = row offset in chunk
        if (anyset(v)) {
            float4 pA = *reinterpret_cast<const float4*>(&s_pred[r][0]);
            float4 pB = *reinterpret_cast<const float4*>(&s_pred[r][4]);
            float p[BB] = {pA.x, pA.y, pA.z, pA.w, pB.x, pB.y, pB.z, pB.w};
            const size_t base = (size_t)(li0 + r) * LL + lj0;
            #pragma unroll
            for (int j = 0; j < 2; j++) {
                if (wordhit(v, j)) {
                    float a = __ldg(&adj[base + j]);
                    cnt[j] += 1.0f;
                    #pragma unroll
                    for (int b = 0; b < BB; b++)
                        acc[b][j] += a * p[b];
                }
            }
        }
    };

    // software pipeline: next UROW batch in flight while current is processed
    VecT cur[UROW];
    #pragma unroll
    for (int u = 0; u < UROW; u++) cur[u] = loadrow(li0 + u);

    for (int li = li0; li < li0 + CHUNK; li += UROW) {
        VecT nxt[UROW];
        const bool has_next = (li + UROW) < (li0 + CHUNK);
        if (has_next) {
            #pragma unroll
            for (int u = 0; u < UROW; u++) nxt[u] = loadrow(li + UROW + u);
        }
        #pragma unroll
        for (int u = 0; u < UROW; u++)
            process(cur[u], li - li0 + u);
        if (has_next) {
            #pragma unroll
            for (int u = 0; u < UROW; u++) cur[u] = nxt[u];
        }
    }

    #pragma unroll
    for (int j = 0; j < 2; j++) {
        atomicAdd(&g_counts[lj0 + j], cnt[j]);
        #pragma unroll
        for (int b = 0; b < BB; b++)
            atomicAdd(&g_numer[b * LL + lj0 + j], acc[b][j]);
    }
}

__global__ __launch_bounds__(TPB, 5) void accum_kernel(
    const float* __restrict__ predicts,
    const float* __restrict__ adj,
    const char*  __restrict__ mask)
{
    const int es = resolve_es(g_flags);   // uniform
    if (es == 1)      accum_body<1>(predicts, adj, mask);
    else if (es == 2) accum_body<2>(predicts, adj, mask);
    else              accum_body<4>(predicts, adj, mask);
}

// ---------------- K2: finalize + fused scalar epilogue ----------------
__device__ __forceinline__ bool mask_nonzero(const char* mask, size_t idx, int es) {
    if (es == 1) return reinterpret_cast<const unsigned char*>(mask)[idx] != 0;
    if (es == 2) return reinterpret_cast<const unsigned short*>(mask)[idx] != 0;
    return reinterpret_cast<const unsigned int*>(mask)[idx] != 0u;
}

__global__ __launch_bounds__(256) void finalize_kernel(
    const float* __restrict__ predicts,
    const float* __restrict__ similarities,
    const char*  __restrict__ mask,
    float* __restrict__ out)
{
    __shared__ float s_sim[BB * BB];
    __shared__ bool s_last;
    if (threadIdx.x < BB * BB) s_sim[threadIdx.x] = similarities[threadIdx.x];
    __syncthreads();

    const int es = resolve_es(g_flags);
    const int lj = blockIdx.x * blockDim.x + threadIdx.x;

    float cand[BB];
    float p_here[BB];
    float dm = mask_nonzero(mask, (size_t)lj * LL + lj, es) ? 1.0f : 0.0f;
    float inv = 1.0f / (g_counts[lj] + (1.0f - dm));
    #pragma unroll
    for (int b = 0; b < BB; b++) {
        p_here[b] = predicts[b * LL + lj];
        cand[b] = (g_numer[b * LL + lj] + (1.0f - dm) * p_here[b]) * inv;
    }

    #pragma unroll
    for (int b = 0; b < BB; b++) {
        float d = p_here[b];
        #pragma unroll
        for (int b2 = 0; b2 < BB; b2++)
            d -= s_sim[b * BB + b2] * cand[b2];
        float v = d * d;
        #pragma unroll
        for (int off = 16; off > 0; off >>= 1)
            v += __shfl_down_sync(0xFFFFFFFFu, v, off);
        if ((threadIdx.x & 31) == 0)
            atomicAdd(&g_sumsq[b], v);
    }

    __threadfence();
    __syncthreads();
    if (threadIdx.x == 0) {
        int t = atomicAdd(&g_done, 1);
        s_last = (t == (int)gridDim.x - 1);
    }
    __syncthreads();
    if (s_last && threadIdx.x == 0) {
        float total = 0.0f, cntv = 0.0f;
        for (int b = 0; b < BB; b++) {
            float rs = 0.0f;
            for (int j = 0; j < BB; j++) rs += s_sim[b * BB + j];
            if (rs != 0.0f) {
                cntv += 1.0f;
                total += sqrtf(*(volatile float*)&g_sumsq[b]);
            }
        }
        out[0] = (cntv == 0.0f) ? 0.0f : (total / fmaxf(cntv, 1.0f));
        g_done = 0;      // reset for graph replay
        g_flags = 0u;
    }
}

// ---------------- launch ----------------
extern "C" void kernel_launch(void* const* d_in, const int* in_sizes, int n_in,
                              void* d_out, int out_size)
{
    const float* predicts = (const float*)d_in[0];
    const float* sim      = (const float*)d_in[1];
    const float* adj      = (const float*)d_in[2];
    const char*  mask     = (const char*)d_in[3];
    float* out = (float*)d_out;

    (void)in_sizes; (void)n_in; (void)out_size;

    prep_kernel<<<304, 256>>>((const unsigned int*)mask);

    dim3 grid1(LL / (TPB * 2), NCHUNK);   // (24, 24) = 576 CTAs
    accum_kernel<<<grid1, TPB>>>(predicts, adj, mask);

    finalize_kernel<<<LL / 256, 256>>>(predicts, sim, mask, out);
}